// round 4
// baseline (speedup 1.0000x reference)
#include <cuda_runtime.h>
#include <cstdint>

#define Bb 16
#define Nn 25200
#define NCc 80
#define KC 1024
#define MAXD 300
#define CONF_T 0.4f
#define IOU_T 0.25f
#define CAP 2048
#define APB 128   // anchors per block in k1

// ---------------- scratch (static device globals; no allocation) ----------------
__device__ float    g_conf[Bb * Nn];      // masked conf (-1 if not candidate)
__device__ int      g_cls [Bb * Nn];      // argmax class
__device__ unsigned g_hist[Bb * 256];     // per-batch conf histogram (built in k1)
__device__ float4   g_box [Bb * KC];      // selected boxes xyxy (sorted by conf desc)
__device__ float    g_cconf[Bb * KC];     // selected conf (0 if slot invalid)
__device__ int      g_ccls[Bb * KC];      // selected class
__device__ unsigned g_mask[Bb * 32 * KC]; // [b][chunk c][col j]: bit i = iou(32c+i,j)>thr && 32c+i<j

// ---------------- kernel 0: zero histograms (graph replays need re-zero) ----------------
__global__ void k0_zero() {
    int i = blockIdx.x * blockDim.x + threadIdx.x;
    if (i < Bb * 256) g_hist[i] = 0u;
}

// ---------------- kernel 1: per-anchor conf/argmax (smem-staged) + histogram ----------------
__global__ __launch_bounds__(APB) void k1_scores(const float* __restrict__ pred) {
    __shared__ float s[APB * 85];
    int t = threadIdx.x;
    const float4* src = (const float4*)(pred + (size_t)blockIdx.x * (APB * 85));
    float4* dst = (float4*)s;
    #pragma unroll 4
    for (int i = t; i < APB * 85 / 4; i += APB) dst[i] = src[i];
    __syncthreads();

    const float* p = s + t * 85;   // stride 85: gcd(85,32)=1 -> conflict-free LDS
    float obj = p[4];
    float m = -1e30f; int arg = 0;
    #pragma unroll
    for (int c = 0; c < NCc; c++) {
        float sc = p[5 + c] * obj;            // exact reference op order
        if (sc > m) { m = sc; arg = c; }      // first-max semantics
    }
    bool cand = (obj > CONF_T) && (m > CONF_T);
    int idx = blockIdx.x * APB + t;
    int b = idx / Nn;
    g_conf[idx] = cand ? m : -1.0f;
    g_cls[idx]  = arg;
    if (cand) {
        unsigned bits = __float_as_uint(m);
        int bk = (int)(bits >> 16) - 0x3ECC;  // conf>0.4 -> bk in [0,179]
        bk = max(0, min(255, bk));
        atomicAdd(&g_hist[b * 256 + bk], 1u);
    }
}

// ---------------- kernel 2: per-batch exact top-1024 (threshold + gather + bitonic) ----------------
__global__ __launch_bounds__(1024) void k2_select(const float* __restrict__ pred) {
    __shared__ unsigned long long skeys[CAP];
    __shared__ unsigned scnt;
    __shared__ int sB1;
    int b = blockIdx.x, tid = threadIdx.x;
    if (tid == 0) {
        scnt = 0u;
        unsigned cum = 0; int bsel = 0;
        for (int kk = 255; kk >= 0; kk--) {
            cum += g_hist[b * 256 + kk];
            if (cum >= KC) { bsel = kk; break; }
        }
        sB1 = bsel;
    }
    __syncthreads();
    int B1 = sB1;

    const float* cf = g_conf + b * Nn;
    for (int n = tid; n < Nn; n += 1024) {
        float c = cf[n];
        if (c > CONF_T) {
            unsigned bits = __float_as_uint(c);
            int bk = (int)(bits >> 16) - 0x3ECC;
            bk = max(0, min(255, bk));
            if (bk >= B1) {
                unsigned pos = atomicAdd(&scnt, 1u);
                if (pos < CAP)
                    skeys[pos] = ((unsigned long long)bits << 32) | (unsigned)(~n);
            }
        }
    }
    __syncthreads();
    unsigned tot = min(scnt, (unsigned)CAP);
    for (int i = tid; i < CAP; i += 1024)
        if ((unsigned)i >= tot) skeys[i] = 0ull;

    // bitonic sort, descending; ties break to smaller index via ~n low bits
    for (int k = 2; k <= CAP; k <<= 1) {
        for (int jj = k >> 1; jj > 0; jj >>= 1) {
            __syncthreads();
            for (int i = tid; i < CAP; i += 1024) {
                int ixj = i ^ jj;
                if (ixj > i) {
                    unsigned long long a = skeys[i], bb = skeys[ixj];
                    bool up = (i & k) == 0;
                    if (up ? (a < bb) : (a > bb)) { skeys[i] = bb; skeys[ixj] = a; }
                }
            }
        }
    }
    __syncthreads();

    // extract top KC, convert boxes xywh->xyxy
    unsigned long long key = skeys[tid];
    unsigned bits = (unsigned)(key >> 32);
    int n = (int)(~(unsigned)(key & 0xFFFFFFFFull));
    float conf = __uint_as_float(bits);
    float4 bx = make_float4(0.f, 0.f, 0.f, 0.f);
    int cls = 0;
    if (conf > CONF_T) {
        const float* p = pred + ((size_t)b * Nn + n) * 85;
        float cx = p[0], cy = p[1], w = p[2], h = p[3];
        bx.x = cx - w * 0.5f; bx.y = cy - h * 0.5f;
        bx.z = cx + w * 0.5f; bx.w = cy + h * 0.5f;
        cls = g_cls[b * Nn + n];
    } else {
        conf = 0.0f;
    }
    g_box  [b * KC + tid] = bx;
    g_cconf[b * KC + tid] = conf;
    g_ccls [b * KC + tid] = cls;
}

// ---------------- kernel 3: IoU bit-matrix, lane-per-row + ballot ----------------
// grid (32 chunks, Bb batches), 1024 threads = 32 warps.
// Warp w covers columns [32w, 32w+32); lane = row index within chunk c.
__global__ __launch_bounds__(1024) void k3_iou() {
    int c = blockIdx.x;
    int b = blockIdx.y;
    int w = threadIdx.x >> 5;
    int lane = threadIdx.x & 31;

    unsigned myword = 0;
    if (w >= c) {
        // row box (this lane's row), held in registers
        float4 ri = g_box[b * KC + c * 32 + lane];
        float ra = (ri.z - ri.x) * (ri.w - ri.y);
        // column box owned by this lane (broadcast source)
        float4 cb = g_box[b * KC + w * 32 + lane];
        float ca = (cb.z - cb.x) * (cb.w - cb.y);

        #pragma unroll
        for (int jj = 0; jj < 32; jj++) {
            float bx0 = __shfl_sync(0xffffffffu, cb.x, jj);
            float by0 = __shfl_sync(0xffffffffu, cb.y, jj);
            float bx1 = __shfl_sync(0xffffffffu, cb.z, jj);
            float by1 = __shfl_sync(0xffffffffu, cb.w, jj);
            float aj  = __shfl_sync(0xffffffffu, ca,  jj);
            float ltx = fmaxf(ri.x, bx0), lty = fmaxf(ri.y, by0);
            float rx  = fminf(ri.z, bx1), ry  = fminf(ri.w, by1);
            float ww = fmaxf(rx - ltx, 0.f), hh = fmaxf(ry - lty, 0.f);
            float inter = ww * hh;
            float iou = inter / (ra + aj - inter + 1e-9f);   // same expr as before (rel_err 0.0)
            unsigned bal = __ballot_sync(0xffffffffu, iou > IOU_T);
            // triangle constraint: bit i only if row 32c+i < col 32w+jj
            unsigned cm = (w > c) ? 0xffffffffu : ((jj == 0) ? 0u : ((1u << jj) - 1u));
            if (lane == jj) myword = bal & cm;
        }
    }
    g_mask[(b * 32 + c) * KC + w * 32 + lane] = myword;
}

// ---------------- kernel 4: greedy NMS (1 barrier per chunk) + output assembly ----------------
__global__ __launch_bounds__(1024) void k4_nms(const int* __restrict__ pimg,
                                               float* __restrict__ out) {
    int b = blockIdx.x, j = threadIdx.x;
    int lane = j & 31, warp = j >> 5;
    float conf = g_cconf[b * KC + j];
    bool alive = conf > CONF_T;            // valid0

    unsigned w[32];
    #pragma unroll
    for (int c = 0; c < 32; c++) w[c] = g_mask[(b * 32 + c) * KC + j];

    __shared__ unsigned skept[32];
    __shared__ unsigned keptall[32];
    __shared__ int snk;

    // pipeline: at iter c, apply chunk c-1's kept mask, then warp c resolves its chunk
    #pragma unroll 1
    for (int c = 0; c < 32; c++) {
        if (c > 0 && warp >= c) alive = alive && !(w[c - 1] & skept[c - 1]);
        if (warp == c) {
            unsigned rem = __ballot_sync(0xffffffffu, alive);
            unsigned W = w[c];             // bits: rows i<j in my chunk that suppress col j
            unsigned kept = 0;
            while (rem) {
                int bs = __ffs(rem) - 1;
                kept |= (1u << bs);
                unsigned row = __ballot_sync(0xffffffffu, (W >> bs) & 1u);
                rem &= ~(1u << bs) & ~row;
            }
            alive = alive && ((kept >> lane) & 1u);
            if (lane == 0) skept[c] = kept;
        }
        __syncthreads();
    }

    unsigned ab = __ballot_sync(0xffffffffu, alive);
    if (lane == 0) keptall[warp] = ab;
    __syncthreads();
    if (j == 0) {
        int s = 0;
        for (int ww = 0; ww < 32; ww++) s += __popc(keptall[ww]);
        snk = s;
    }
    __syncthreads();
    int nk = snk;
    int rank = 0;
    for (int ww = 0; ww < warp; ww++) rank += __popc(keptall[ww]);
    rank += __popc(keptall[warp] & ((1u << lane) - 1u));

    // output layout: dets[16*300*6] | valid[16*300] | feats[300*82]
    float* dets  = out;
    float* valid = out + Bb * MAXD * 6;
    float* feats = out + Bb * MAXD * 6 + Bb * MAXD;

    float fimg = 640.0f;
    if (pimg) {
        int iv = *pimg;
        fimg = (iv > 0 && iv < (1 << 20)) ? (float)iv : __int_as_float(iv);
    }
    float scale = 1.0f / fimg;

    for (int r = j; r < MAXD; r += 1024) {
        bool v = r < nk;
        if (!v) {
            #pragma unroll
            for (int q = 0; q < 6; q++) dets[((size_t)b * MAXD + r) * 6 + q] = 0.f;
        }
        valid[b * MAXD + r] = v ? 1.0f : 0.0f;
    }
    if (b == 0) {
        for (int i = j; i < MAXD * (NCc + 2); i += 1024) feats[i] = 0.f;
    }
    __syncthreads();

    // kept items: rank r < 300 written (kept-first stable order == index order)
    if (alive && rank < MAXD) {
        float4 bx = g_box[b * KC + j];
        int cls = g_ccls[b * KC + j];
        float* dr = dets + ((size_t)b * MAXD + rank) * 6;
        dr[0] = bx.x; dr[1] = bx.y; dr[2] = bx.z; dr[3] = bx.w;
        dr[4] = conf; dr[5] = (float)cls;
        if (b == 0) {
            float cx = (bx.x + bx.z) * 0.5f * scale;
            float cy = (bx.y + bx.w) * 0.5f * scale;
            feats[rank * (NCc + 2) + 0] = cx;
            feats[rank * (NCc + 2) + 1] = cy;
            feats[rank * (NCc + 2) + 2 + cls] = 1.0f;
        }
    }
}

// ---------------- launch ----------------
extern "C" void kernel_launch(void* const* d_in, const int* in_sizes, int n_in,
                              void* d_out, int out_size) {
    const float* pred = (const float*)d_in[0];
    const int* pimg = (n_in >= 2) ? (const int*)d_in[1] : nullptr;
    float* out = (float*)d_out;

    k0_zero<<<(Bb * 256 + 255) / 256, 256>>>();
    k1_scores<<<(Bb * Nn) / APB, APB>>>(pred);
    k2_select<<<Bb, 1024>>>(pred);
    k3_iou<<<dim3(32, Bb), 1024>>>();
    k4_nms<<<Bb, 1024>>>(pimg, out);
}

// round 5
// speedup vs baseline: 1.2158x; 1.2158x over previous
#include <cuda_runtime.h>
#include <cstdint>

#define Bb 16
#define Nn 25200
#define NCc 80
#define KC 1024
#define MAXD 300
#define CONF_T 0.4f
#define IOU_T 0.25f
#define CAP 2048
#define APB 128            // anchors per block in k1
#define K1_BYTES (APB * 85 * 4)   // 43520, %16 == 0

// ---------------- scratch (static device globals; no allocation) ----------------
__device__ float    g_conf[Bb * Nn];
__device__ int      g_cls [Bb * Nn];
__device__ unsigned g_hist[Bb * 256];
__device__ float4   g_box [Bb * KC];
__device__ float    g_cconf[Bb * KC];
__device__ int      g_ccls[Bb * KC];
__device__ unsigned g_mask[Bb * 32 * KC];

__device__ __forceinline__ unsigned smem_u32(const void* p) {
    unsigned a;
    asm("{ .reg .u64 t; cvta.to.shared.u64 t, %1; cvt.u32.u64 %0, t; }" : "=r"(a) : "l"(p));
    return a;
}
__device__ __forceinline__ void mbar_init(unsigned m, unsigned cnt) {
    asm volatile("mbarrier.init.shared.b64 [%0], %1;" :: "r"(m), "r"(cnt) : "memory");
}
__device__ __forceinline__ void mbar_expect_tx(unsigned m, unsigned bytes) {
    asm volatile("mbarrier.arrive.expect_tx.shared.b64 _, [%0], %1;" :: "r"(m), "r"(bytes) : "memory");
}
__device__ __forceinline__ void bulk_g2s(unsigned dst, const void* src, unsigned bytes, unsigned m) {
    asm volatile("cp.async.bulk.shared::cluster.global.mbarrier::complete_tx::bytes [%0], [%1], %2, [%3];"
                 :: "r"(dst), "l"(src), "r"(bytes), "r"(m) : "memory");
}
__device__ __forceinline__ void mbar_wait(unsigned m, unsigned parity) {
    asm volatile(
        "{\n\t.reg .pred P;\n\t"
        "WL_%=:\n\t"
        "mbarrier.try_wait.parity.acquire.cta.shared::cta.b64 P, [%0], %1, 0x989680;\n\t"
        "@P bra.uni WD_%=;\n\t"
        "bra.uni WL_%=;\n\t"
        "WD_%=:\n\t}"
        :: "r"(m), "r"(parity) : "memory");
}

// ---------------- kernel 0: zero histograms ----------------
__global__ void k0_zero() {
    int i = blockIdx.x * blockDim.x + threadIdx.x;
    if (i < Bb * 256) g_hist[i] = 0u;
}

// ---------------- kernel 1: TMA-staged, 4 anchors/thread, vector LDS ----------------
__global__ __launch_bounds__(32) void k1_scores(const float* __restrict__ pred) {
    __shared__ __align__(16) float s[APB * 85];
    __shared__ __align__(8) unsigned long long mbar;
    int t = threadIdx.x;
    unsigned mb = smem_u32(&mbar);
    if (t == 0) mbar_init(mb, 1);
    __syncthreads();
    if (t == 0) {
        mbar_expect_tx(mb, K1_BYTES);
        bulk_g2s(smem_u32(s), pred + (size_t)blockIdx.x * (APB * 85), K1_BYTES, mb);
    }
    mbar_wait(mb, 0);

    // thread t handles anchors 4t..4t+3 (340 floats = 85 aligned float4, conflict-free)
    const float4* sv = (const float4*)s + t * 85;
    float m[4] = {-1e30f, -1e30f, -1e30f, -1e30f};
    float obj[4] = {0.f, 0.f, 0.f, 0.f};
    int   arg[4] = {0, 0, 0, 0};
    #pragma unroll
    for (int sl = 0; sl < 85; sl++) {
        float4 v = sv[sl];
        float vals[4] = {v.x, v.y, v.z, v.w};
        #pragma unroll
        for (int e = 0; e < 4; e++) {
            const int flat = 4 * sl + e;
            const int a = flat / 85;
            const int c = flat - 85 * a;
            float val = vals[e];
            if (c == 4) obj[a] = val;
            else if (c >= 5) {
                float sc = val * obj[a];              // exact reference op order
                if (sc > m[a]) { m[a] = sc; arg[a] = c - 5; }  // first-max
            }
        }
    }

    int gbase = blockIdx.x * APB + 4 * t;   // 4 anchors, same batch (Nn%4==0)
    int b = gbase / Nn;
    float cf[4]; int cl[4];
    #pragma unroll
    for (int a = 0; a < 4; a++) {
        bool cand = (obj[a] > CONF_T) && (m[a] > CONF_T);
        cf[a] = cand ? m[a] : -1.0f;
        cl[a] = arg[a];
        if (cand) {
            unsigned bits = __float_as_uint(m[a]);
            int bk = (int)(bits >> 16) - 0x3ECC;
            bk = max(0, min(255, bk));
            atomicAdd(&g_hist[b * 256 + bk], 1u);
        }
    }
    *(float4*)(g_conf + gbase) = make_float4(cf[0], cf[1], cf[2], cf[3]);
    *(int4*)  (g_cls  + gbase) = make_int4(cl[0], cl[1], cl[2], cl[3]);
}

// ---------------- kernel 2: per-batch exact top-1024 ----------------
__global__ __launch_bounds__(1024) void k2_select(const float* __restrict__ pred) {
    __shared__ unsigned long long skeys[CAP];
    __shared__ unsigned scnt;
    __shared__ int sB1;
    int b = blockIdx.x, tid = threadIdx.x;
    if (tid == 0) {
        scnt = 0u;
        unsigned cum = 0; int bsel = 0;
        for (int kk = 255; kk >= 0; kk--) {
            cum += g_hist[b * 256 + kk];
            if (cum >= KC) { bsel = kk; break; }
        }
        sB1 = bsel;
    }
    __syncthreads();
    int B1 = sB1;

    const float* cf = g_conf + b * Nn;
    for (int n = tid; n < Nn; n += 1024) {
        float c = cf[n];
        if (c > CONF_T) {
            unsigned bits = __float_as_uint(c);
            int bk = (int)(bits >> 16) - 0x3ECC;
            bk = max(0, min(255, bk));
            if (bk >= B1) {
                unsigned pos = atomicAdd(&scnt, 1u);
                if (pos < CAP)
                    skeys[pos] = ((unsigned long long)bits << 32) | (unsigned)(~n);
            }
        }
    }
    __syncthreads();
    unsigned tot = min(scnt, (unsigned)CAP);
    for (int i = tid; i < CAP; i += 1024)
        if ((unsigned)i >= tot) skeys[i] = 0ull;

    for (int k = 2; k <= CAP; k <<= 1) {
        for (int jj = k >> 1; jj > 0; jj >>= 1) {
            __syncthreads();
            for (int i = tid; i < CAP; i += 1024) {
                int ixj = i ^ jj;
                if (ixj > i) {
                    unsigned long long a = skeys[i], bb = skeys[ixj];
                    bool up = (i & k) == 0;
                    if (up ? (a < bb) : (a > bb)) { skeys[i] = bb; skeys[ixj] = a; }
                }
            }
        }
    }
    __syncthreads();

    unsigned long long key = skeys[tid];
    unsigned bits = (unsigned)(key >> 32);
    int n = (int)(~(unsigned)(key & 0xFFFFFFFFull));
    float conf = __uint_as_float(bits);
    float4 bx = make_float4(0.f, 0.f, 0.f, 0.f);
    int cls = 0;
    if (conf > CONF_T) {
        const float* p = pred + ((size_t)b * Nn + n) * 85;
        float cx = p[0], cy = p[1], w = p[2], h = p[3];
        bx.x = cx - w * 0.5f; bx.y = cy - h * 0.5f;
        bx.z = cx + w * 0.5f; bx.w = cy + h * 0.5f;
        cls = g_cls[b * Nn + n];
    } else {
        conf = 0.0f;
    }
    g_box  [b * KC + tid] = bx;
    g_cconf[b * KC + tid] = conf;
    g_ccls [b * KC + tid] = cls;
}

// ---------------- kernel 3: IoU bit-matrix (smem broadcast, div-free fast path) ----------------
__global__ __launch_bounds__(1024) void k3_iou() {
    __shared__ float4 s_box[KC];
    __shared__ float  s_area[KC];
    int c = blockIdx.x;     // row chunk
    int b = blockIdx.y;
    int tid = threadIdx.x;
    int w = tid >> 5, lane = tid & 31;

    float4 v = g_box[b * KC + tid];
    s_box[tid] = v;
    s_area[tid] = (v.z - v.x) * (v.w - v.y);
    __syncthreads();

    unsigned myword = 0;
    if (w >= c) {
        float4 ri = s_box[c * 32 + lane];     // this lane's row box (registers)
        float ra = s_area[c * 32 + lane];
        #pragma unroll 4
        for (int jj = 0; jj < 32; jj++) {
            int col = w * 32 + jj;
            float4 cb = s_box[col];           // broadcast LDS
            float aj = s_area[col];
            float ltx = fmaxf(ri.x, cb.x), lty = fmaxf(ri.y, cb.y);
            float rx  = fminf(ri.z, cb.z), ry  = fminf(ri.w, cb.w);
            float ww = fmaxf(rx - ltx, 0.f), hh = fmaxf(ry - lty, 0.f);
            float inter = ww * hh;
            float d = ra + aj - inter + 1e-9f;
            float diff = fmaf(-IOU_T, d, inter);     // sign test for iou > IOU_T
            bool sup;
            bool near = fabsf(diff) < 1e-4f * d;
            if (__any_sync(0xffffffffu, near)) {
                sup = (inter / d) > IOU_T;           // exact reference path (rare)
            } else {
                sup = diff > 0.0f;
            }
            unsigned bal = __ballot_sync(0xffffffffu, sup);
            unsigned cm = (w > c) ? 0xffffffffu : ((jj == 0) ? 0u : ((1u << jj) - 1u));
            if (lane == jj) myword = bal & cm;
        }
    }
    g_mask[(b * 32 + c) * KC + tid] = myword;
}

// ---------------- kernel 4: greedy NMS (1 barrier per chunk) + outputs ----------------
__global__ __launch_bounds__(1024) void k4_nms(const int* __restrict__ pimg,
                                               float* __restrict__ out) {
    int b = blockIdx.x, j = threadIdx.x;
    int lane = j & 31, warp = j >> 5;
    float conf = g_cconf[b * KC + j];
    bool alive = conf > CONF_T;

    unsigned w[32];
    #pragma unroll
    for (int c = 0; c < 32; c++) w[c] = g_mask[(b * 32 + c) * KC + j];

    __shared__ unsigned skept[32];
    __shared__ unsigned keptall[32];
    __shared__ int snk;

    #pragma unroll 1
    for (int c = 0; c < 32; c++) {
        if (c > 0 && warp >= c) alive = alive && !(w[c - 1] & skept[c - 1]);
        if (warp == c) {
            unsigned rem = __ballot_sync(0xffffffffu, alive);
            unsigned W = w[c];
            unsigned kept = 0;
            while (rem) {
                int bs = __ffs(rem) - 1;
                kept |= (1u << bs);
                unsigned row = __ballot_sync(0xffffffffu, (W >> bs) & 1u);
                rem &= ~(1u << bs) & ~row;
            }
            alive = alive && ((kept >> lane) & 1u);
            if (lane == 0) skept[c] = kept;
        }
        __syncthreads();
    }

    unsigned ab = __ballot_sync(0xffffffffu, alive);
    if (lane == 0) keptall[warp] = ab;
    __syncthreads();
    if (j == 0) {
        int s = 0;
        for (int ww = 0; ww < 32; ww++) s += __popc(keptall[ww]);
        snk = s;
    }
    __syncthreads();
    int nk = snk;
    int rank = 0;
    for (int ww = 0; ww < warp; ww++) rank += __popc(keptall[ww]);
    rank += __popc(keptall[warp] & ((1u << lane) - 1u));

    float* dets  = out;
    float* valid = out + Bb * MAXD * 6;
    float* feats = out + Bb * MAXD * 6 + Bb * MAXD;

    float fimg = 640.0f;
    if (pimg) {
        int iv = *pimg;
        fimg = (iv > 0 && iv < (1 << 20)) ? (float)iv : __int_as_float(iv);
    }
    float scale = 1.0f / fimg;

    for (int r = j; r < MAXD; r += 1024) {
        bool v = r < nk;
        if (!v) {
            #pragma unroll
            for (int q = 0; q < 6; q++) dets[((size_t)b * MAXD + r) * 6 + q] = 0.f;
        }
        valid[b * MAXD + r] = v ? 1.0f : 0.0f;
    }
    if (b == 0) {
        for (int i = j; i < MAXD * (NCc + 2); i += 1024) feats[i] = 0.f;
    }
    __syncthreads();

    if (alive && rank < MAXD) {
        float4 bx = g_box[b * KC + j];
        int cls = g_ccls[b * KC + j];
        float* dr = dets + ((size_t)b * MAXD + rank) * 6;
        dr[0] = bx.x; dr[1] = bx.y; dr[2] = bx.z; dr[3] = bx.w;
        dr[4] = conf; dr[5] = (float)cls;
        if (b == 0) {
            float cx = (bx.x + bx.z) * 0.5f * scale;
            float cy = (bx.y + bx.w) * 0.5f * scale;
            feats[rank * (NCc + 2) + 0] = cx;
            feats[rank * (NCc + 2) + 1] = cy;
            feats[rank * (NCc + 2) + 2 + cls] = 1.0f;
        }
    }
}

// ---------------- launch ----------------
extern "C" void kernel_launch(void* const* d_in, const int* in_sizes, int n_in,
                              void* d_out, int out_size) {
    const float* pred = (const float*)d_in[0];
    const int* pimg = (n_in >= 2) ? (const int*)d_in[1] : nullptr;
    float* out = (float*)d_out;

    k0_zero<<<(Bb * 256 + 255) / 256, 256>>>();
    k1_scores<<<(Bb * Nn) / APB, 32>>>(pred);
    k2_select<<<Bb, 1024>>>(pred);
    k3_iou<<<dim3(32, Bb), 1024>>>();
    k4_nms<<<Bb, 1024>>>(pimg, out);
}

// round 6
// speedup vs baseline: 1.3409x; 1.1029x over previous
#include <cuda_runtime.h>
#include <cstdint>

#define Bb 16
#define Nn 25200
#define NCc 80
#define KC 1024
#define MAXD 300
#define CONF_T 0.4f
#define IOU_T 0.25f
#define CAP 2048
#define APB 128                   // anchors per block in k1
#define K1_BYTES (APB * 85 * 4)   // 43520, %16 == 0
#define NTASK 528                 // 32*33/2 upper-triangle chunk pairs

// ---------------- scratch (static device globals; no allocation) ----------------
__device__ float    g_conf[Bb * Nn];
__device__ int      g_cls [Bb * Nn];
__device__ unsigned g_hist[Bb * 256];     // zero-init at load; re-zeroed by k2 each call
__device__ float4   g_box [Bb * KC];
__device__ float    g_cconf[Bb * KC];
__device__ int      g_ccls[Bb * KC];
__device__ unsigned g_mask[Bb * 32 * KC]; // lower triangle stays 0 (static init, never written)

__device__ __forceinline__ unsigned smem_u32(const void* p) {
    unsigned a;
    asm("{ .reg .u64 t; cvta.to.shared.u64 t, %1; cvt.u32.u64 %0, t; }" : "=r"(a) : "l"(p));
    return a;
}
__device__ __forceinline__ void mbar_init(unsigned m, unsigned cnt) {
    asm volatile("mbarrier.init.shared.b64 [%0], %1;" :: "r"(m), "r"(cnt) : "memory");
}
__device__ __forceinline__ void mbar_expect_tx(unsigned m, unsigned bytes) {
    asm volatile("mbarrier.arrive.expect_tx.shared.b64 _, [%0], %1;" :: "r"(m), "r"(bytes) : "memory");
}
__device__ __forceinline__ void bulk_g2s(unsigned dst, const void* src, unsigned bytes, unsigned m) {
    asm volatile("cp.async.bulk.shared::cluster.global.mbarrier::complete_tx::bytes [%0], [%1], %2, [%3];"
                 :: "r"(dst), "l"(src), "r"(bytes), "r"(m) : "memory");
}
__device__ __forceinline__ void mbar_wait(unsigned m, unsigned parity) {
    asm volatile(
        "{\n\t.reg .pred P;\n\t"
        "WL_%=:\n\t"
        "mbarrier.try_wait.parity.acquire.cta.shared::cta.b64 P, [%0], %1, 0x989680;\n\t"
        "@P bra.uni WD_%=;\n\t"
        "bra.uni WL_%=;\n\t"
        "WD_%=:\n\t}"
        :: "r"(m), "r"(parity) : "memory");
}

// ---------------- k1: TMA-staged, 1 anchor/thread, warp-uniform alignment ----------------
// Anchor a starts at float 85a = 4*S + O, O = a%4. Warp q handles anchors {4*lane+q},
// so O == q is warp-uniform; proc<O> extracts elements at compile-time offsets.
template<int O>
__device__ __forceinline__ void proc1(const float4* sv, float& obj, float& m, int& arg) {
    m = -1e30f; arg = 0; obj = 0.f;
    #pragma unroll
    for (int s = 1; s <= 21; s++) {
        float4 f = sv[s];
        float e[4] = {f.x, f.y, f.z, f.w};
        #pragma unroll
        for (int q = 0; q < 4; q++) {
            const int j = 4 * s + q - O;   // element index within anchor
            if (j == 4) obj = e[q];
            else if (j >= 5 && j <= 84) {
                float sc = e[q] * obj;               // exact reference op order
                if (sc > m) { m = sc; arg = j - 5; } // first-max semantics
            }
        }
    }
}

__global__ __launch_bounds__(128) void k1_scores(const float* __restrict__ pred) {
    __shared__ __align__(16) float s[APB * 85];
    __shared__ __align__(8) unsigned long long mbar;
    int t = threadIdx.x;
    int q = t >> 5, lane = t & 31;
    unsigned mb = smem_u32(&mbar);
    if (t == 0) mbar_init(mb, 1);
    __syncthreads();
    if (t == 0) {
        mbar_expect_tx(mb, K1_BYTES);
        bulk_g2s(smem_u32(s), pred + (size_t)blockIdx.x * (APB * 85), K1_BYTES, mb);
    }
    mbar_wait(mb, 0);

    int a = 4 * lane + q;                        // anchor within tile; a%4 == q
    int S = (85 * a - q) >> 2;                   // first float4 slot of anchor
    const float4* sv = (const float4*)s + S;
    float obj, m; int arg;
    if      (q == 0) proc1<0>(sv, obj, m, arg);
    else if (q == 1) proc1<1>(sv, obj, m, arg);
    else if (q == 2) proc1<2>(sv, obj, m, arg);
    else             proc1<3>(sv, obj, m, arg);

    int idx = blockIdx.x * APB + a;
    int b = idx / Nn;
    bool cand = (obj > CONF_T) && (m > CONF_T);
    g_conf[idx] = cand ? m : -1.0f;
    g_cls[idx]  = arg;
    if (cand) {
        unsigned bits = __float_as_uint(m);
        int bk = (int)(bits >> 16) - 0x3ECC;     // conf>0.4 -> monotone bucket
        bk = max(0, min(255, bk));
        atomicAdd(&g_hist[b * 256 + bk], 1u);
    }
}

// ---------------- k2: per-batch exact top-1024 (suffix-sum threshold + gather + bitonic) ----------------
__global__ __launch_bounds__(1024) void k2_select(const float* __restrict__ pred) {
    __shared__ unsigned long long skeys[CAP];
    __shared__ unsigned shist[256];
    __shared__ unsigned scnt;
    __shared__ int sB1;
    int b = blockIdx.x, tid = threadIdx.x;
    if (tid == 0) { scnt = 0u; sB1 = 0; }
    if (tid < 256) {
        shist[tid] = g_hist[b * 256 + tid];
        g_hist[b * 256 + tid] = 0u;              // re-zero for next call (replaces k0)
    }
    __syncthreads();
    // suffix sum: shist[k] = #candidates in buckets >= k
    #pragma unroll
    for (int off = 1; off < 256; off <<= 1) {
        unsigned v = 0;
        if (tid < 256) { v = shist[tid]; if (tid + off < 256) v += shist[tid + off]; }
        __syncthreads();
        if (tid < 256) shist[tid] = v;
        __syncthreads();
    }
    if (tid < 256) {
        if (shist[tid] >= KC && (tid == 255 || shist[tid + 1] < KC)) sB1 = tid;
    }
    __syncthreads();
    int B1 = sB1;

    const float* cf = g_conf + b * Nn;
    for (int n = tid; n < Nn; n += 1024) {
        float c = cf[n];
        if (c > CONF_T) {
            unsigned bits = __float_as_uint(c);
            int bk = (int)(bits >> 16) - 0x3ECC;
            bk = max(0, min(255, bk));
            if (bk >= B1) {
                unsigned pos = atomicAdd(&scnt, 1u);
                if (pos < CAP)
                    skeys[pos] = ((unsigned long long)bits << 32) | (unsigned)(~n);
            }
        }
    }
    __syncthreads();
    unsigned tot = min(scnt, (unsigned)CAP);
    for (int i = tid; i < CAP; i += 1024)
        if ((unsigned)i >= tot) skeys[i] = 0ull;

    for (int k = 2; k <= CAP; k <<= 1) {
        for (int jj = k >> 1; jj > 0; jj >>= 1) {
            __syncthreads();
            for (int i = tid; i < CAP; i += 1024) {
                int ixj = i ^ jj;
                if (ixj > i) {
                    unsigned long long a = skeys[i], bb = skeys[ixj];
                    bool up = (i & k) == 0;
                    if (up ? (a < bb) : (a > bb)) { skeys[i] = bb; skeys[ixj] = a; }
                }
            }
        }
    }
    __syncthreads();

    unsigned long long key = skeys[tid];
    unsigned bits = (unsigned)(key >> 32);
    int n = (int)(~(unsigned)(key & 0xFFFFFFFFull));
    float conf = __uint_as_float(bits);
    float4 bx = make_float4(0.f, 0.f, 0.f, 0.f);
    int cls = 0;
    if (conf > CONF_T) {
        const float* p = pred + ((size_t)b * Nn + n) * 85;
        float cx = p[0], cy = p[1], w = p[2], h = p[3];
        bx.x = cx - w * 0.5f; bx.y = cy - h * 0.5f;
        bx.z = cx + w * 0.5f; bx.w = cy + h * 0.5f;
        cls = g_cls[b * Nn + n];
    } else {
        conf = 0.0f;
    }
    g_box  [b * KC + tid] = bx;
    g_cconf[b * KC + tid] = conf;
    g_ccls [b * KC + tid] = cls;
}

// ---------------- k3: IoU bit-matrix, triangle-packed warps ----------------
// 17 blocks/batch x 32 warps = 544 warp slots covering the 528 (c,w) upper-triangle tasks.
__global__ __launch_bounds__(1024) void k3_iou() {
    __shared__ float4 s_box[KC];
    __shared__ float  s_area[KC];
    int b = blockIdx.y;
    int tid = threadIdx.x;
    int wid = tid >> 5, lane = tid & 31;

    float4 v = g_box[b * KC + tid];
    s_box[tid] = v;
    s_area[tid] = (v.z - v.x) * (v.w - v.y);
    __syncthreads();

    int t = blockIdx.x * 32 + wid;
    if (t < NTASK) {
        // map t -> (c, wcol) over pairs {(c,w): w >= c}
        int c = 0, rem = t;
        while (rem >= 32 - c) { rem -= 32 - c; c++; }
        int wcol = c + rem;

        float4 ri = s_box[c * 32 + lane];
        float ra = s_area[c * 32 + lane];
        unsigned myword = 0;
        #pragma unroll 4
        for (int jj = 0; jj < 32; jj++) {
            int col = wcol * 32 + jj;
            float4 cb = s_box[col];
            float aj = s_area[col];
            float ltx = fmaxf(ri.x, cb.x), lty = fmaxf(ri.y, cb.y);
            float rx  = fminf(ri.z, cb.z), ry  = fminf(ri.w, cb.w);
            float ww = fmaxf(rx - ltx, 0.f), hh = fmaxf(ry - lty, 0.f);
            float inter = ww * hh;
            float d = ra + aj - inter + 1e-9f;
            float diff = fmaf(-IOU_T, d, inter);     // sign test for iou > IOU_T
            bool sup;
            bool near = fabsf(diff) < 1e-4f * d;
            if (__any_sync(0xffffffffu, near)) {
                sup = (inter / d) > IOU_T;           // exact reference path (rare)
            } else {
                sup = diff > 0.0f;
            }
            unsigned bal = __ballot_sync(0xffffffffu, sup);
            unsigned cm = (wcol > c) ? 0xffffffffu : ((jj == 0) ? 0u : ((1u << jj) - 1u));
            if (lane == jj) myword = bal & cm;
        }
        g_mask[(b * 32 + c) * KC + wcol * 32 + lane] = myword;
    }
}

// ---------------- k4: greedy NMS (1 barrier per chunk) + outputs ----------------
__global__ __launch_bounds__(1024) void k4_nms(const int* __restrict__ pimg,
                                               float* __restrict__ out) {
    int b = blockIdx.x, j = threadIdx.x;
    int lane = j & 31, warp = j >> 5;
    float conf = g_cconf[b * KC + j];
    bool alive = conf > CONF_T;

    unsigned w[32];
    #pragma unroll
    for (int c = 0; c < 32; c++) w[c] = g_mask[(b * 32 + c) * KC + j];

    __shared__ unsigned skept[32];
    __shared__ unsigned keptall[32];
    __shared__ int snk;

    #pragma unroll 1
    for (int c = 0; c < 32; c++) {
        if (c > 0 && warp >= c) alive = alive && !(w[c - 1] & skept[c - 1]);
        if (warp == c) {
            unsigned rem = __ballot_sync(0xffffffffu, alive);
            unsigned W = w[c];
            unsigned kept = 0;
            while (rem) {
                int bs = __ffs(rem) - 1;
                kept |= (1u << bs);
                unsigned row = __ballot_sync(0xffffffffu, (W >> bs) & 1u);
                rem &= ~(1u << bs) & ~row;
            }
            alive = alive && ((kept >> lane) & 1u);
            if (lane == 0) skept[c] = kept;
        }
        __syncthreads();
    }

    unsigned ab = __ballot_sync(0xffffffffu, alive);
    if (lane == 0) keptall[warp] = ab;
    __syncthreads();
    if (j == 0) {
        int s = 0;
        for (int ww = 0; ww < 32; ww++) s += __popc(keptall[ww]);
        snk = s;
    }
    __syncthreads();
    int nk = snk;
    int rank = 0;
    for (int ww = 0; ww < warp; ww++) rank += __popc(keptall[ww]);
    rank += __popc(keptall[warp] & ((1u << lane) - 1u));

    float* dets  = out;
    float* valid = out + Bb * MAXD * 6;
    float* feats = out + Bb * MAXD * 6 + Bb * MAXD;

    float fimg = 640.0f;
    if (pimg) {
        int iv = *pimg;
        fimg = (iv > 0 && iv < (1 << 20)) ? (float)iv : __int_as_float(iv);
    }
    float scale = 1.0f / fimg;

    for (int r = j; r < MAXD; r += 1024) {
        bool v = r < nk;
        if (!v) {
            #pragma unroll
            for (int q = 0; q < 6; q++) dets[((size_t)b * MAXD + r) * 6 + q] = 0.f;
        }
        valid[b * MAXD + r] = v ? 1.0f : 0.0f;
    }
    if (b == 0) {
        for (int i = j; i < MAXD * (NCc + 2); i += 1024) feats[i] = 0.f;
    }
    __syncthreads();

    if (alive && rank < MAXD) {
        float4 bx = g_box[b * KC + j];
        int cls = g_ccls[b * KC + j];
        float* dr = dets + ((size_t)b * MAXD + rank) * 6;
        dr[0] = bx.x; dr[1] = bx.y; dr[2] = bx.z; dr[3] = bx.w;
        dr[4] = conf; dr[5] = (float)cls;
        if (b == 0) {
            float cx = (bx.x + bx.z) * 0.5f * scale;
            float cy = (bx.y + bx.w) * 0.5f * scale;
            feats[rank * (NCc + 2) + 0] = cx;
            feats[rank * (NCc + 2) + 1] = cy;
            feats[rank * (NCc + 2) + 2 + cls] = 1.0f;
        }
    }
}

// ---------------- launch ----------------
extern "C" void kernel_launch(void* const* d_in, const int* in_sizes, int n_in,
                              void* d_out, int out_size) {
    const float* pred = (const float*)d_in[0];
    const int* pimg = (n_in >= 2) ? (const int*)d_in[1] : nullptr;
    float* out = (float*)d_out;

    k1_scores<<<(Bb * Nn) / APB, 128>>>(pred);
    k2_select<<<Bb, 1024>>>(pred);
    k3_iou<<<dim3(17, Bb), 1024>>>();
    k4_nms<<<Bb, 1024>>>(pimg, out);
}